// round 13
// baseline (speedup 1.0000x reference)
#include <cuda_runtime.h>

#define N_NODES 65536
#define CF      16
#define L0      4097
#define SFC     2
#define LAT     128
#define HID     512
#define BATCH   16
#define KS      32
#define L1OUT   16385
#define NROWS   131104

// -------- scratch --------
__device__ float g_h1[HID * BATCH];                 // [512][16]
__device__ float g_a [SFC * CF * L0 * BATCH];       // [i][ci][l][b]
__device__ float g_c0[SFC * CF * L1OUT * BATCH];    // [i][ci][l][b]
__device__ float g_c1[SFC * N_NODES * BATCH];       // [i][o][b]

__device__ __forceinline__ void dfma2(float2 &acc, float2 w, float2 x) {
    asm("{\n\t"
        ".reg .b64 a,b,c;\n\t"
        "mov.b64 a, {%2,%3};\n\t"
        "mov.b64 b, {%4,%5};\n\t"
        "mov.b64 c, {%0,%1};\n\t"
        "fma.rn.f32x2 c, a, b, c;\n\t"
        "mov.b64 {%0,%1}, c;\n\t"
        "}"
        : "+f"(acc.x), "+f"(acc.y)
        : "f"(w.x), "f"(w.y), "f"(x.x), "f"(x.y));
}

__device__ __forceinline__ void cp_async16(void* smem, const void* gmem) {
    unsigned s = (unsigned)__cvta_generic_to_shared(smem);
    asm volatile("cp.async.cg.shared.global [%0], [%1], 16;" :: "r"(s), "l"(gmem));
}

// spacer: with ONE nop the profiled (4th) launch is k_conv0
__global__ void k_nop() {}

// ---------------- Stage 1 ----------------
__global__ __launch_bounds__(256) void k_gemm1(
    const float* __restrict__ x, const float* __restrict__ W1,
    const float* __restrict__ b1)
{
    __shared__ float xs[BATCH * LAT];
    int tid = threadIdx.x;
    for (int t = tid; t < BATCH * LAT; t += 256) xs[t] = x[t];
    __syncthreads();

    int b = tid & 15;
    int j = blockIdx.x * 16 + (tid >> 4);
    const float4* w4 = (const float4*)(W1 + j * LAT);
    const float4* xv = (const float4*)(xs + b * LAT);
    float acc = 0.f;
#pragma unroll
    for (int c = 0; c < LAT / 4; c++) {
        float4 w = w4[c], xx = xv[c];
        acc += w.x * xx.x + w.y * xx.y + w.z * xx.z + w.w * xx.w;
    }
    g_h1[j * BATCH + b] = tanhf(acc + b1[j]);
}

// ---------------- Stage 2: 8-rows/thread + per-warp cp.async ring (R12, validated 62.5us) ----------------
#define G2_HS4  2176                     // 128*17 float4
#define G2_RW4  128                      // 8 rows * 16 f4 per warp-stage
#define G2_STG  3
#define G2_SMEM ((G2_HS4 + 8 * G2_STG * G2_RW4) * 16)   // 83,968 B

__global__ __launch_bounds__(256) void k_gemm2(
    const float* __restrict__ W2, const float* __restrict__ b2)
{
    extern __shared__ float4 dyn4[];
    float4* hs4  = dyn4;
    float4* ring = dyn4 + G2_HS4;        // [warp][stage][128]

    int tid  = threadIdx.x;
    int lane = tid & 31, warp = tid >> 5;
    int c    = lane & 15, bh = lane >> 4;
    int row0 = blockIdx.x * 64 + warp * 8;

    for (int t = tid; t < 2048; t += 256) {
        int k = t >> 2, m = t & 3;
        hs4[(k >> 2) * 17 + (k & 3) * 4 + m] = ((const float4*)g_h1)[t];
    }
    __syncthreads();

    const float4* W4 = (const float4*)W2;
    float4* wring = ring + warp * (G2_STG * G2_RW4);

    int slot[4]; size_t g[4];
#pragma unroll
    for (int m = 0; m < 4; m++) {
        int e = lane + 32 * m;
        int u = e >> 4, ci = e & 15;
        int r = row0 + u; if (r > NROWS - 1) r = NROWS - 1;
        g[m]    = (size_t)r * 128 + ci;
        slot[m] = u * 16 + ci;
    }

#pragma unroll
    for (int s = 0; s < 2; s++) {
#pragma unroll
        for (int m = 0; m < 4; m++)
            cp_async16(&wring[s * G2_RW4 + slot[m]], W4 + g[m] + s * 16);
        asm volatile("cp.async.commit_group;");
    }

    float2 acc[8][4];
#pragma unroll
    for (int u = 0; u < 8; u++)
#pragma unroll
        for (int p = 0; p < 4; p++) acc[u][p] = make_float2(0.f, 0.f);

#pragma unroll 1
    for (int jj = 0; jj < 8; jj++) {
        asm volatile("cp.async.wait_group 1;" ::: "memory");
        __syncwarp();
        if (jj + 2 < 8) {
            int st = (jj + 2) % 3;
#pragma unroll
            for (int m = 0; m < 4; m++)
                cp_async16(&wring[st * G2_RW4 + slot[m]], W4 + g[m] + (jj + 2) * 16);
        }
        asm volatile("cp.async.commit_group;");

        const float4* wt = &wring[(jj % 3) * G2_RW4];
        const float4* hq = &hs4[(16 * jj + c) * 17 + 2 * bh];

        float4 hh[8];
#pragma unroll
        for (int kk = 0; kk < 4; kk++) {
            hh[2 * kk]     = hq[kk * 4];
            hh[2 * kk + 1] = hq[kk * 4 + 1];
        }
#pragma unroll
        for (int u = 0; u < 8; u++) {
            float4 w = wt[u * 16 + c];
#pragma unroll
            for (int kk = 0; kk < 4; kk++) {
                float wv = (kk == 0) ? w.x : (kk == 1) ? w.y : (kk == 2) ? w.z : w.w;
                float2 w2 = make_float2(wv, wv);
                float4 h0 = hh[2 * kk], h1 = hh[2 * kk + 1];
                dfma2(acc[u][0], w2, make_float2(h0.x, h0.y));
                dfma2(acc[u][1], w2, make_float2(h0.z, h0.w));
                dfma2(acc[u][2], w2, make_float2(h1.x, h1.y));
                dfma2(acc[u][3], w2, make_float2(h1.z, h1.w));
            }
        }
    }

    // reduce-scatter: rows over masks 4,2,1; pairs over 8
    float2 r4[4][4];
    {
        bool hi = (lane & 4) != 0;
#pragma unroll
        for (int u = 0; u < 4; u++)
#pragma unroll
            for (int p = 0; p < 4; p++) {
                float2 give = hi ? acc[u][p] : acc[u + 4][p];
                float2 mine = hi ? acc[u + 4][p] : acc[u][p];
                float2 got;
                got.x = __shfl_xor_sync(0xffffffffu, give.x, 4);
                got.y = __shfl_xor_sync(0xffffffffu, give.y, 4);
                r4[u][p] = make_float2(mine.x + got.x, mine.y + got.y);
            }
    }
    float2 r2[2][4];
    {
        bool hi = (lane & 2) != 0;
#pragma unroll
        for (int u = 0; u < 2; u++)
#pragma unroll
            for (int p = 0; p < 4; p++) {
                float2 give = hi ? r4[u][p] : r4[u + 2][p];
                float2 mine = hi ? r4[u + 2][p] : r4[u][p];
                float2 got;
                got.x = __shfl_xor_sync(0xffffffffu, give.x, 2);
                got.y = __shfl_xor_sync(0xffffffffu, give.y, 2);
                r2[u][p] = make_float2(mine.x + got.x, mine.y + got.y);
            }
    }
    float2 r1[4];
    {
        bool hi = (lane & 1) != 0;
#pragma unroll
        for (int p = 0; p < 4; p++) {
            float2 give = hi ? r2[0][p] : r2[1][p];
            float2 mine = hi ? r2[1][p] : r2[0][p];
            float2 got;
            got.x = __shfl_xor_sync(0xffffffffu, give.x, 1);
            got.y = __shfl_xor_sync(0xffffffffu, give.y, 1);
            r1[p] = make_float2(mine.x + got.x, mine.y + got.y);
        }
    }
    float2 rf[2];
    {
        bool hi = (lane & 8) != 0;
#pragma unroll
        for (int p = 0; p < 2; p++) {
            float2 give = hi ? r1[p] : r1[p + 2];
            float2 mine = hi ? r1[p + 2] : r1[p];
            float2 got;
            got.x = __shfl_xor_sync(0xffffffffu, give.x, 8);
            got.y = __shfl_xor_sync(0xffffffffu, give.y, 8);
            rf[p] = make_float2(mine.x + got.x, mine.y + got.y);
        }
    }

    int r = row0 + (lane & 7);
    if (r < NROWS) {
        float bias = b2[r];
        int i = r & 1, rem = r >> 1;
        int cc = rem / L0, l = rem - cc * L0;
        float4 o;
        o.x = tanhf(rf[0].x + bias);
        o.y = tanhf(rf[0].y + bias);
        o.z = tanhf(rf[1].x + bias);
        o.w = tanhf(rf[1].y + bias);
        *(float4*)&g_a[(size_t)((i * CF + cc) * L0 + l) * BATCH + 4 * (lane >> 3)] = o;
    }
}

// ---------------- Stage 3: ConvT #0 (16->16) + tanh, q-tile 8 ----------------
// j=8: each weight-LDS feeds 8 FMA2; per-ci FMA issue (512 cyc) covers the
// 15-load L2 window (~260 cyc). Double-buffered inv over ci.
__global__ __launch_bounds__(128) void k_conv0(
    const float* __restrict__ ctw0, const float* __restrict__ ctb0)
{
    int i   = blockIdx.y;
    int tid = threadIdx.x;
    __shared__ float ws[CF * CF * 33];
    for (int t = tid; t < CF * CF * KS; t += 128) {
        int ci = t >> 9, co = (t >> 5) & 15, k = t & 31;
        ws[(ci * 16 + co) * 33 + k] = ctw0[i * (CF * CF * KS) + t];
    }
    __syncthreads();

    int bp = tid & 7;
    int co = tid >> 3;
    int q0 = blockIdx.x * 8;

    float2 acc[8][4];
#pragma unroll
    for (int j = 0; j < 8; j++)
#pragma unroll
        for (int ph = 0; ph < 4; ph++) acc[j][ph] = make_float2(0.f, 0.f);

    float2 inv[2][15];
    {
        const float* src = g_a + (size_t)(i * CF * L0) * BATCH + 2 * bp;
#pragma unroll
        for (int t = 0; t < 15; t++) {
            int l = q0 - 3 + t;
            inv[0][t] = (l >= 0 && l <= L0 - 1) ? *(const float2*)(src + (size_t)l * BATCH)
                                                : make_float2(0.f, 0.f);
        }
    }

#pragma unroll
    for (int ci = 0; ci < CF; ci++) {
        int cur = ci & 1;
        if (ci + 1 < CF) {
            const float* src = g_a + (size_t)((i * CF + ci + 1) * L0) * BATCH + 2 * bp;
#pragma unroll
            for (int t = 0; t < 15; t++) {
                int l = q0 - 3 + t;
                inv[cur ^ 1][t] = (l >= 0 && l <= L0 - 1)
                    ? *(const float2*)(src + (size_t)l * BATCH) : make_float2(0.f, 0.f);
            }
        }
        const float* wsp = &ws[(ci * 16 + co) * 33];
#pragma unroll
        for (int s = 0; s < 8; s++)
#pragma unroll
            for (int ph = 0; ph < 4; ph++) {
                float wv = wsp[ph + 4 * s];
                float2 w2 = make_float2(wv, wv);
#pragma unroll
                for (int j = 0; j < 8; j++) dfma2(acc[j][ph], w2, inv[cur][j + 7 - s]);
            }
    }

    float bias = ctb0[i * CF + co];
#pragma unroll
    for (int j = 0; j < 8; j++)
#pragma unroll
        for (int ph = 0; ph < 4; ph++) {
            int o = 4 * (q0 + j) + ph;
            if (o < L1OUT) {
                float2 v;
                v.x = tanhf(acc[j][ph].x + bias);
                v.y = tanhf(acc[j][ph].y + bias);
                *(float2*)&g_c0[(size_t)((i * CF + co) * L1OUT + o) * BATCH + 2 * bp] = v;
            }
        }
}

// ---------------- Stage 4: ConvT #1 (16->1) + tanh (measured-best direct) ----------------
__global__ __launch_bounds__(256) void k_conv1(
    const float* __restrict__ ctw1, const float* __restrict__ ctb1)
{
    int i   = blockIdx.y;
    int tid = threadIdx.x;
    __shared__ float wv[CF * KS];
    for (int t = tid; t < CF * KS; t += 256) wv[t] = ctw1[i * (CF * KS) + t];
    __syncthreads();

    int bp = tid & 7;
    int qi = tid >> 3;
    int q  = blockIdx.x * 128 + qi * 4;

    float2 acc[4][4];
#pragma unroll
    for (int j = 0; j < 4; j++)
#pragma unroll
        for (int ph = 0; ph < 4; ph++) acc[j][ph] = make_float2(0.f, 0.f);

#pragma unroll 1
    for (int ci = 0; ci < CF; ci++) {
        const float* src = g_c0 + (size_t)((i * CF + ci) * L1OUT) * BATCH + 2 * bp;
        float2 inv[11];
#pragma unroll
        for (int t = 0; t < 11; t++) {
            int l = q - 3 + t;
            inv[t] = (l >= 0 && l <= L1OUT - 1) ? *(const float2*)(src + (size_t)l * BATCH)
                                                : make_float2(0.f, 0.f);
        }
        const float* wp = &wv[ci * 32];
#pragma unroll
        for (int s = 0; s < 8; s++)
#pragma unroll
            for (int ph = 0; ph < 4; ph++) {
                float2 w2 = make_float2(wp[ph + 4 * s], wp[ph + 4 * s]);
#pragma unroll
                for (int j = 0; j < 4; j++) dfma2(acc[j][ph], w2, inv[j + 7 - s]);
            }
    }

    float bias = ctb1[i];
#pragma unroll
    for (int j = 0; j < 4; j++)
#pragma unroll
        for (int ph = 0; ph < 4; ph++) {
            int o = 4 * (q + j) + ph;
            float2 v;
            v.x = tanhf(acc[j][ph].x + bias);
            v.y = tanhf(acc[j][ph].y + bias);
            *(float2*)&g_c1[(size_t)(i * N_NODES + o) * BATCH + 2 * bp] = v;
        }
}

// ---------------- Stage 5: gather + combine ----------------
__global__ __launch_bounds__(256) void k_gather(
    const float* __restrict__ sps_w, const float* __restrict__ sps_b,
    const float* __restrict__ final_w, const float* __restrict__ final_b,
    const float* __restrict__ out_w, const float* __restrict__ out_b,
    const int* __restrict__ ord, float* __restrict__ out)
{
    __shared__ float gs[SFC][258][17];
    int tid = threadIdx.x;
    int n0  = blockIdx.x * 256;

    for (int t = tid; t < SFC * 258; t += 256) {
        int i  = (t >= 258);
        int tt = t - i * 258;
        int n  = n0 - 1 + tt;
        n = n < 0 ? 0 : (n > N_NODES - 1 ? N_NODES - 1 : n);
        int idx = ord[i * N_NODES + n];
        const float4* s4 = (const float4*)&g_c1[(size_t)(i * N_NODES + idx) * BATCH];
        float tmp[16];
        *(float4*)&tmp[0]  = s4[0];
        *(float4*)&tmp[4]  = s4[1];
        *(float4*)&tmp[8]  = s4[2];
        *(float4*)&tmp[12] = s4[3];
        float* row = gs[i][tt];
#pragma unroll
        for (int b = 0; b < 16; b++) row[b] = tmp[b];
    }
    __syncthreads();

    int n = n0 + tid;
    float w[SFC][3], sb[SFC];
#pragma unroll
    for (int i = 0; i < SFC; i++) {
        const float* wp = &sps_w[(size_t)(i * N_NODES + n) * 3];
        w[i][0] = wp[0]; w[i][1] = wp[1]; w[i][2] = wp[2];
        sb[i] = sps_b[i * N_NODES + n];
    }
    float fw0 = final_w[2 * n], fw1 = final_w[2 * n + 1];
    float fb = final_b[n], ow = out_w[n], ob = out_b[n];

#pragma unroll
    for (int b = 0; b < BATCH; b++) {
        float z0 = tanhf(gs[0][tid][b] * w[0][0] + gs[0][tid + 1][b] * w[0][1]
                       + gs[0][tid + 2][b] * w[0][2] + sb[0]);
        float z1 = tanhf(gs[1][tid][b] * w[1][0] + gs[1][tid + 1][b] * w[1][1]
                       + gs[1][tid + 2][b] * w[1][2] + sb[1]);
        float zz = tanhf(z0 * fw0 + z1 * fw1 + fb);
        out[(size_t)b * N_NODES + n] = zz * ow + ob;
    }
}

// ---------------- launch ----------------
extern "C" void kernel_launch(void* const* d_in, const int* in_sizes, int n_in,
                              void* d_out, int out_size)
{
    const float* x       = (const float*)d_in[0];
    const float* W1      = (const float*)d_in[1];
    const float* b1      = (const float*)d_in[2];
    const float* W2      = (const float*)d_in[3];
    const float* b2      = (const float*)d_in[4];
    const float* ctw0    = (const float*)d_in[5];
    const float* ctb0    = (const float*)d_in[6];
    const float* ctw1    = (const float*)d_in[7];
    const float* ctb1    = (const float*)d_in[8];
    const float* sps_w   = (const float*)d_in[9];
    const float* sps_b   = (const float*)d_in[10];
    const float* final_w = (const float*)d_in[11];
    const float* final_b = (const float*)d_in[12];
    const float* out_w   = (const float*)d_in[13];
    const float* out_b   = (const float*)d_in[14];
    const int*   ord     = (const int*)d_in[15];
    float* out = (float*)d_out;

    static int smem_set = 0;
    if (!smem_set) {
        cudaFuncSetAttribute(k_gemm2, cudaFuncAttributeMaxDynamicSharedMemorySize,
                             G2_SMEM);
        smem_set = 1;
    }

    k_gemm1<<<32, 256>>>(x, W1, b1);
    k_nop<<<1, 32>>>();   // single spacer: profiled slot (4th launch) = k_conv0
    k_gemm2<<<(NROWS + 63) / 64, 256, G2_SMEM>>>(W2, b2);
    k_conv0<<<dim3(513, SFC), 128>>>(ctw0, ctb0);
    k_conv1<<<dim3(128, SFC), 256>>>(ctw1, ctb1);
    k_gather<<<dim3(256, 1), 256>>>(sps_w, sps_b, final_w, final_b,
                                    out_w, out_b, ord, out);
}

// round 14
// speedup vs baseline: 1.1276x; 1.1276x over previous
#include <cuda_runtime.h>

#define N_NODES 65536
#define CF      16
#define L0      4097
#define SFC     2
#define LAT     128
#define HID     512
#define BATCH   16
#define KS      32
#define L1OUT   16385
#define NROWS   131104

// -------- scratch --------
__device__ float g_h1[HID * BATCH];                 // [512][16]
__device__ float g_a [SFC * CF * L0 * BATCH];       // [i][ci][l][b]
__device__ float g_c0[SFC * CF * L1OUT * BATCH];    // [i][ci][l][b]
__device__ float g_c1[SFC * N_NODES * BATCH];       // [i][o][b]

__device__ __forceinline__ void dfma2(float2 &acc, float2 w, float2 x) {
    asm("{\n\t"
        ".reg .b64 a,b,c;\n\t"
        "mov.b64 a, {%2,%3};\n\t"
        "mov.b64 b, {%4,%5};\n\t"
        "mov.b64 c, {%0,%1};\n\t"
        "fma.rn.f32x2 c, a, b, c;\n\t"
        "mov.b64 {%0,%1}, c;\n\t"
        "}"
        : "+f"(acc.x), "+f"(acc.y)
        : "f"(w.x), "f"(w.y), "f"(x.x), "f"(x.y));
}

__device__ __forceinline__ void cp_async16(void* smem, const void* gmem) {
    unsigned s = (unsigned)__cvta_generic_to_shared(smem);
    asm volatile("cp.async.cg.shared.global [%0], [%1], 16;" :: "r"(s), "l"(gmem));
}

// spacer: with ONE nop the profiled (4th) launch is k_conv0
__global__ void k_nop() {}

// ---------------- Stage 1 ----------------
__global__ __launch_bounds__(256) void k_gemm1(
    const float* __restrict__ x, const float* __restrict__ W1,
    const float* __restrict__ b1)
{
    __shared__ float xs[BATCH * LAT];
    int tid = threadIdx.x;
    for (int t = tid; t < BATCH * LAT; t += 256) xs[t] = x[t];
    __syncthreads();

    int b = tid & 15;
    int j = blockIdx.x * 16 + (tid >> 4);
    const float4* w4 = (const float4*)(W1 + j * LAT);
    const float4* xv = (const float4*)(xs + b * LAT);
    float acc = 0.f;
#pragma unroll
    for (int c = 0; c < LAT / 4; c++) {
        float4 w = w4[c], xx = xv[c];
        acc += w.x * xx.x + w.y * xx.y + w.z * xx.z + w.w * xx.w;
    }
    g_h1[j * BATCH + b] = tanhf(acc + b1[j]);
}

// ---------------- Stage 2: 8-rows/thread + per-warp cp.async ring (validated 62.5us) ----------------
#define G2_HS4  2176
#define G2_RW4  128
#define G2_STG  3
#define G2_SMEM ((G2_HS4 + 8 * G2_STG * G2_RW4) * 16)

__global__ __launch_bounds__(256) void k_gemm2(
    const float* __restrict__ W2, const float* __restrict__ b2)
{
    extern __shared__ float4 dyn4[];
    float4* hs4  = dyn4;
    float4* ring = dyn4 + G2_HS4;

    int tid  = threadIdx.x;
    int lane = tid & 31, warp = tid >> 5;
    int c    = lane & 15, bh = lane >> 4;
    int row0 = blockIdx.x * 64 + warp * 8;

    for (int t = tid; t < 2048; t += 256) {
        int k = t >> 2, m = t & 3;
        hs4[(k >> 2) * 17 + (k & 3) * 4 + m] = ((const float4*)g_h1)[t];
    }
    __syncthreads();

    const float4* W4 = (const float4*)W2;
    float4* wring = ring + warp * (G2_STG * G2_RW4);

    int slot[4]; size_t g[4];
#pragma unroll
    for (int m = 0; m < 4; m++) {
        int e = lane + 32 * m;
        int u = e >> 4, ci = e & 15;
        int r = row0 + u; if (r > NROWS - 1) r = NROWS - 1;
        g[m]    = (size_t)r * 128 + ci;
        slot[m] = u * 16 + ci;
    }

#pragma unroll
    for (int s = 0; s < 2; s++) {
#pragma unroll
        for (int m = 0; m < 4; m++)
            cp_async16(&wring[s * G2_RW4 + slot[m]], W4 + g[m] + s * 16);
        asm volatile("cp.async.commit_group;");
    }

    float2 acc[8][4];
#pragma unroll
    for (int u = 0; u < 8; u++)
#pragma unroll
        for (int p = 0; p < 4; p++) acc[u][p] = make_float2(0.f, 0.f);

#pragma unroll 1
    for (int jj = 0; jj < 8; jj++) {
        asm volatile("cp.async.wait_group 1;" ::: "memory");
        __syncwarp();
        if (jj + 2 < 8) {
            int st = (jj + 2) % 3;
#pragma unroll
            for (int m = 0; m < 4; m++)
                cp_async16(&wring[st * G2_RW4 + slot[m]], W4 + g[m] + (jj + 2) * 16);
        }
        asm volatile("cp.async.commit_group;");

        const float4* wt = &wring[(jj % 3) * G2_RW4];
        const float4* hq = &hs4[(16 * jj + c) * 17 + 2 * bh];

        float4 hh[8];
#pragma unroll
        for (int kk = 0; kk < 4; kk++) {
            hh[2 * kk]     = hq[kk * 4];
            hh[2 * kk + 1] = hq[kk * 4 + 1];
        }
#pragma unroll
        for (int u = 0; u < 8; u++) {
            float4 w = wt[u * 16 + c];
#pragma unroll
            for (int kk = 0; kk < 4; kk++) {
                float wv = (kk == 0) ? w.x : (kk == 1) ? w.y : (kk == 2) ? w.z : w.w;
                float2 w2 = make_float2(wv, wv);
                float4 h0 = hh[2 * kk], h1 = hh[2 * kk + 1];
                dfma2(acc[u][0], w2, make_float2(h0.x, h0.y));
                dfma2(acc[u][1], w2, make_float2(h0.z, h0.w));
                dfma2(acc[u][2], w2, make_float2(h1.x, h1.y));
                dfma2(acc[u][3], w2, make_float2(h1.z, h1.w));
            }
        }
    }

    // reduce-scatter: rows over masks 4,2,1; pairs over 8
    float2 r4[4][4];
    {
        bool hi = (lane & 4) != 0;
#pragma unroll
        for (int u = 0; u < 4; u++)
#pragma unroll
            for (int p = 0; p < 4; p++) {
                float2 give = hi ? acc[u][p] : acc[u + 4][p];
                float2 mine = hi ? acc[u + 4][p] : acc[u][p];
                float2 got;
                got.x = __shfl_xor_sync(0xffffffffu, give.x, 4);
                got.y = __shfl_xor_sync(0xffffffffu, give.y, 4);
                r4[u][p] = make_float2(mine.x + got.x, mine.y + got.y);
            }
    }
    float2 r2[2][4];
    {
        bool hi = (lane & 2) != 0;
#pragma unroll
        for (int u = 0; u < 2; u++)
#pragma unroll
            for (int p = 0; p < 4; p++) {
                float2 give = hi ? r4[u][p] : r4[u + 2][p];
                float2 mine = hi ? r4[u + 2][p] : r4[u][p];
                float2 got;
                got.x = __shfl_xor_sync(0xffffffffu, give.x, 2);
                got.y = __shfl_xor_sync(0xffffffffu, give.y, 2);
                r2[u][p] = make_float2(mine.x + got.x, mine.y + got.y);
            }
    }
    float2 r1[4];
    {
        bool hi = (lane & 1) != 0;
#pragma unroll
        for (int p = 0; p < 4; p++) {
            float2 give = hi ? r2[0][p] : r2[1][p];
            float2 mine = hi ? r2[1][p] : r2[0][p];
            float2 got;
            got.x = __shfl_xor_sync(0xffffffffu, give.x, 1);
            got.y = __shfl_xor_sync(0xffffffffu, give.y, 1);
            r1[p] = make_float2(mine.x + got.x, mine.y + got.y);
        }
    }
    float2 rf[2];
    {
        bool hi = (lane & 8) != 0;
#pragma unroll
        for (int p = 0; p < 2; p++) {
            float2 give = hi ? r1[p] : r1[p + 2];
            float2 mine = hi ? r1[p + 2] : r1[p];
            float2 got;
            got.x = __shfl_xor_sync(0xffffffffu, give.x, 8);
            got.y = __shfl_xor_sync(0xffffffffu, give.y, 8);
            rf[p] = make_float2(mine.x + got.x, mine.y + got.y);
        }
    }

    int r = row0 + (lane & 7);
    if (r < NROWS) {
        float bias = b2[r];
        int i = r & 1, rem = r >> 1;
        int cc = rem / L0, l = rem - cc * L0;
        float4 o;
        o.x = tanhf(rf[0].x + bias);
        o.y = tanhf(rf[0].y + bias);
        o.z = tanhf(rf[1].x + bias);
        o.w = tanhf(rf[1].y + bias);
        *(float4*)&g_a[(size_t)((i * CF + cc) * L0 + l) * BATCH + 4 * (lane >> 3)] = o;
    }
}

// ---------------- Stage 3: ConvT #0 (16->16) + tanh — R12 j=4 (known-good) ----------------
__global__ __launch_bounds__(128) void k_conv0(
    const float* __restrict__ ctw0, const float* __restrict__ ctb0)
{
    int i   = blockIdx.y;
    int tid = threadIdx.x;
    __shared__ float ws[CF * CF * 33];
    for (int t = tid; t < CF * CF * KS; t += 128) {
        int ci = t >> 9, co = (t >> 5) & 15, k = t & 31;
        ws[(ci * 16 + co) * 33 + k] = ctw0[i * (CF * CF * KS) + t];
    }
    __syncthreads();

    int bp = tid & 7;
    int co = tid >> 3;
    int q0 = blockIdx.x * 4;

    float2 acc[4][4];
#pragma unroll
    for (int j = 0; j < 4; j++)
#pragma unroll
        for (int ph = 0; ph < 4; ph++) acc[j][ph] = make_float2(0.f, 0.f);

    float2 inv[2][11];
    {
        const float* src = g_a + (size_t)(i * CF * L0) * BATCH + 2 * bp;
#pragma unroll
        for (int t = 0; t < 11; t++) {
            int l = q0 - 3 + t;
            inv[0][t] = (l >= 0 && l <= L0 - 1) ? *(const float2*)(src + (size_t)l * BATCH)
                                                : make_float2(0.f, 0.f);
        }
    }

#pragma unroll
    for (int ci = 0; ci < CF; ci++) {
        int cur = ci & 1;
        if (ci + 1 < CF) {
            const float* src = g_a + (size_t)((i * CF + ci + 1) * L0) * BATCH + 2 * bp;
#pragma unroll
            for (int t = 0; t < 11; t++) {
                int l = q0 - 3 + t;
                inv[cur ^ 1][t] = (l >= 0 && l <= L0 - 1)
                    ? *(const float2*)(src + (size_t)l * BATCH) : make_float2(0.f, 0.f);
            }
        }
        const float* wsp = &ws[(ci * 16 + co) * 33];
#pragma unroll
        for (int s = 0; s < 8; s++)
#pragma unroll
            for (int ph = 0; ph < 4; ph++) {
                float wv = wsp[ph + 4 * s];
                float2 w2 = make_float2(wv, wv);
#pragma unroll
                for (int j = 0; j < 4; j++) dfma2(acc[j][ph], w2, inv[cur][j + 7 - s]);
            }
    }

    float bias = ctb0[i * CF + co];
#pragma unroll
    for (int j = 0; j < 4; j++)
#pragma unroll
        for (int ph = 0; ph < 4; ph++) {
            int o = 4 * (q0 + j) + ph;
            if (o < L1OUT) {
                float2 v;
                v.x = tanhf(acc[j][ph].x + bias);
                v.y = tanhf(acc[j][ph].y + bias);
                *(float2*)&g_c0[(size_t)((i * CF + co) * L1OUT + o) * BATCH + 2 * bp] = v;
            }
        }
}

// ---------------- Stage 4: ConvT #1 (16->1) + tanh — j=1 high-occupancy ----------------
// 256 thr = 32 qi x 8 bp, 1 q/thread. acc 8 regs -> ~55 regs -> ~40 resident
// warps/SM; in-flight LDG ~20KB/SM clears the 13.6KB MLP threshold.
__global__ __launch_bounds__(256) void k_conv1(
    const float* __restrict__ ctw1, const float* __restrict__ ctb1)
{
    int i   = blockIdx.y;
    int tid = threadIdx.x;
    __shared__ float wv[CF * KS];
    for (int t = tid; t < CF * KS; t += 256) wv[t] = ctw1[i * (CF * KS) + t];
    __syncthreads();

    int bp = tid & 7;
    int qi = tid >> 3;                    // 0..31
    int q  = blockIdx.x * 32 + qi;        // 512 blocks x 32 q = 16384

    float2 acc[4];
#pragma unroll
    for (int ph = 0; ph < 4; ph++) acc[ph] = make_float2(0.f, 0.f);

#pragma unroll 1
    for (int ci = 0; ci < CF; ci++) {
        const float* src = g_c0 + (size_t)((i * CF + ci) * L1OUT) * BATCH + 2 * bp;
        float2 inv[8];
#pragma unroll
        for (int t = 0; t < 8; t++) {
            int l = q - 3 + t;
            inv[t] = (l >= 0 && l <= L1OUT - 1) ? *(const float2*)(src + (size_t)l * BATCH)
                                                : make_float2(0.f, 0.f);
        }
        const float* wp = &wv[ci * 32];
#pragma unroll
        for (int s = 0; s < 8; s++)
#pragma unroll
            for (int ph = 0; ph < 4; ph++) {
                float2 w2 = make_float2(wp[ph + 4 * s], wp[ph + 4 * s]);
                dfma2(acc[ph], w2, inv[7 - s]);
            }
    }

    float bias = ctb1[i];
#pragma unroll
    for (int ph = 0; ph < 4; ph++) {
        int o = 4 * q + ph;
        float2 v;
        v.x = tanhf(acc[ph].x + bias);
        v.y = tanhf(acc[ph].y + bias);
        *(float2*)&g_c1[(size_t)(i * N_NODES + o) * BATCH + 2 * bp] = v;
    }
}

// ---------------- Stage 5: gather + combine ----------------
__global__ __launch_bounds__(256) void k_gather(
    const float* __restrict__ sps_w, const float* __restrict__ sps_b,
    const float* __restrict__ final_w, const float* __restrict__ final_b,
    const float* __restrict__ out_w, const float* __restrict__ out_b,
    const int* __restrict__ ord, float* __restrict__ out)
{
    __shared__ float gs[SFC][258][17];
    int tid = threadIdx.x;
    int n0  = blockIdx.x * 256;

    for (int t = tid; t < SFC * 258; t += 256) {
        int i  = (t >= 258);
        int tt = t - i * 258;
        int n  = n0 - 1 + tt;
        n = n < 0 ? 0 : (n > N_NODES - 1 ? N_NODES - 1 : n);
        int idx = ord[i * N_NODES + n];
        const float4* s4 = (const float4*)&g_c1[(size_t)(i * N_NODES + idx) * BATCH];
        float tmp[16];
        *(float4*)&tmp[0]  = s4[0];
        *(float4*)&tmp[4]  = s4[1];
        *(float4*)&tmp[8]  = s4[2];
        *(float4*)&tmp[12] = s4[3];
        float* row = gs[i][tt];
#pragma unroll
        for (int b = 0; b < 16; b++) row[b] = tmp[b];
    }
    __syncthreads();

    int n = n0 + tid;
    float w[SFC][3], sb[SFC];
#pragma unroll
    for (int i = 0; i < SFC; i++) {
        const float* wp = &sps_w[(size_t)(i * N_NODES + n) * 3];
        w[i][0] = wp[0]; w[i][1] = wp[1]; w[i][2] = wp[2];
        sb[i] = sps_b[i * N_NODES + n];
    }
    float fw0 = final_w[2 * n], fw1 = final_w[2 * n + 1];
    float fb = final_b[n], ow = out_w[n], ob = out_b[n];

#pragma unroll
    for (int b = 0; b < BATCH; b++) {
        float z0 = tanhf(gs[0][tid][b] * w[0][0] + gs[0][tid + 1][b] * w[0][1]
                       + gs[0][tid + 2][b] * w[0][2] + sb[0]);
        float z1 = tanhf(gs[1][tid][b] * w[1][0] + gs[1][tid + 1][b] * w[1][1]
                       + gs[1][tid + 2][b] * w[1][2] + sb[1]);
        float zz = tanhf(z0 * fw0 + z1 * fw1 + fb);
        out[(size_t)b * N_NODES + n] = zz * ow + ob;
    }
}

// ---------------- launch ----------------
extern "C" void kernel_launch(void* const* d_in, const int* in_sizes, int n_in,
                              void* d_out, int out_size)
{
    const float* x       = (const float*)d_in[0];
    const float* W1      = (const float*)d_in[1];
    const float* b1      = (const float*)d_in[2];
    const float* W2      = (const float*)d_in[3];
    const float* b2      = (const float*)d_in[4];
    const float* ctw0    = (const float*)d_in[5];
    const float* ctb0    = (const float*)d_in[6];
    const float* ctw1    = (const float*)d_in[7];
    const float* ctb1    = (const float*)d_in[8];
    const float* sps_w   = (const float*)d_in[9];
    const float* sps_b   = (const float*)d_in[10];
    const float* final_w = (const float*)d_in[11];
    const float* final_b = (const float*)d_in[12];
    const float* out_w   = (const float*)d_in[13];
    const float* out_b   = (const float*)d_in[14];
    const int*   ord     = (const int*)d_in[15];
    float* out = (float*)d_out;

    static int smem_set = 0;
    if (!smem_set) {
        cudaFuncSetAttribute(k_gemm2, cudaFuncAttributeMaxDynamicSharedMemorySize,
                             G2_SMEM);
        smem_set = 1;
    }

    k_gemm1<<<32, 256>>>(x, W1, b1);
    k_nop<<<1, 32>>>();   // single spacer: profiled slot (4th launch) = k_conv0 (j=4)
    k_gemm2<<<(NROWS + 63) / 64, 256, G2_SMEM>>>(W2, b2);
    k_conv0<<<dim3(1025, SFC), 128>>>(ctw0, ctb0);
    k_conv1<<<dim3(512, SFC), 256>>>(ctw1, ctb1);
    k_gather<<<dim3(256, 1), 256>>>(sps_w, sps_b, final_w, final_b,
                                    out_w, out_b, ord, out);
}

// round 15
// speedup vs baseline: 1.1967x; 1.0613x over previous
#include <cuda_runtime.h>

#define N_NODES 65536
#define CF      16
#define L0      4097
#define SFC     2
#define LAT     128
#define HID     512
#define BATCH   16
#define KS      32
#define L1OUT   16385
#define NROWS   131104

// -------- scratch --------
__device__ float g_h1[HID * BATCH];                 // [512][16]
__device__ float g_a [SFC * CF * L0 * BATCH];       // [i][ci][l][b]
__device__ float g_c0[SFC * CF * L1OUT * BATCH];    // [i][ci][l][b]
__device__ float g_c1[SFC * N_NODES * BATCH];       // [i][o][b]

__device__ __forceinline__ void dfma2(float2 &acc, float2 w, float2 x) {
    asm("{\n\t"
        ".reg .b64 a,b,c;\n\t"
        "mov.b64 a, {%2,%3};\n\t"
        "mov.b64 b, {%4,%5};\n\t"
        "mov.b64 c, {%0,%1};\n\t"
        "fma.rn.f32x2 c, a, b, c;\n\t"
        "mov.b64 {%0,%1}, c;\n\t"
        "}"
        : "+f"(acc.x), "+f"(acc.y)
        : "f"(w.x), "f"(w.y), "f"(x.x), "f"(x.y));
}

__device__ __forceinline__ void cp_async16(void* smem, const void* gmem) {
    unsigned s = (unsigned)__cvta_generic_to_shared(smem);
    asm volatile("cp.async.cg.shared.global [%0], [%1], 16;" :: "r"(s), "l"(gmem));
}

// spacer: with ONE nop the profiled (4th) launch is k_conv0
__global__ void k_nop() {}

// ---------------- Stage 1 ----------------
__global__ __launch_bounds__(256) void k_gemm1(
    const float* __restrict__ x, const float* __restrict__ W1,
    const float* __restrict__ b1)
{
    __shared__ float xs[BATCH * LAT];
    int tid = threadIdx.x;
    for (int t = tid; t < BATCH * LAT; t += 256) xs[t] = x[t];
    __syncthreads();

    int b = tid & 15;
    int j = blockIdx.x * 16 + (tid >> 4);
    const float4* w4 = (const float4*)(W1 + j * LAT);
    const float4* xv = (const float4*)(xs + b * LAT);
    float acc = 0.f;
#pragma unroll
    for (int c = 0; c < LAT / 4; c++) {
        float4 w = w4[c], xx = xv[c];
        acc += w.x * xx.x + w.y * xx.y + w.z * xx.z + w.w * xx.w;
    }
    g_h1[j * BATCH + b] = tanhf(acc + b1[j]);
}

// ---------------- Stage 2: 8-rows/thread + per-warp cp.async ring (validated 62.5us) ----------------
#define G2_HS4  2176
#define G2_RW4  128
#define G2_STG  3
#define G2_SMEM ((G2_HS4 + 8 * G2_STG * G2_RW4) * 16)

__global__ __launch_bounds__(256) void k_gemm2(
    const float* __restrict__ W2, const float* __restrict__ b2)
{
    extern __shared__ float4 dyn4[];
    float4* hs4  = dyn4;
    float4* ring = dyn4 + G2_HS4;

    int tid  = threadIdx.x;
    int lane = tid & 31, warp = tid >> 5;
    int c    = lane & 15, bh = lane >> 4;
    int row0 = blockIdx.x * 64 + warp * 8;

    for (int t = tid; t < 2048; t += 256) {
        int k = t >> 2, m = t & 3;
        hs4[(k >> 2) * 17 + (k & 3) * 4 + m] = ((const float4*)g_h1)[t];
    }
    __syncthreads();

    const float4* W4 = (const float4*)W2;
    float4* wring = ring + warp * (G2_STG * G2_RW4);

    int slot[4]; size_t g[4];
#pragma unroll
    for (int m = 0; m < 4; m++) {
        int e = lane + 32 * m;
        int u = e >> 4, ci = e & 15;
        int r = row0 + u; if (r > NROWS - 1) r = NROWS - 1;
        g[m]    = (size_t)r * 128 + ci;
        slot[m] = u * 16 + ci;
    }

#pragma unroll
    for (int s = 0; s < 2; s++) {
#pragma unroll
        for (int m = 0; m < 4; m++)
            cp_async16(&wring[s * G2_RW4 + slot[m]], W4 + g[m] + s * 16);
        asm volatile("cp.async.commit_group;");
    }

    float2 acc[8][4];
#pragma unroll
    for (int u = 0; u < 8; u++)
#pragma unroll
        for (int p = 0; p < 4; p++) acc[u][p] = make_float2(0.f, 0.f);

#pragma unroll 1
    for (int jj = 0; jj < 8; jj++) {
        asm volatile("cp.async.wait_group 1;" ::: "memory");
        __syncwarp();
        if (jj + 2 < 8) {
            int st = (jj + 2) % 3;
#pragma unroll
            for (int m = 0; m < 4; m++)
                cp_async16(&wring[st * G2_RW4 + slot[m]], W4 + g[m] + (jj + 2) * 16);
        }
        asm volatile("cp.async.commit_group;");

        const float4* wt = &wring[(jj % 3) * G2_RW4];
        const float4* hq = &hs4[(16 * jj + c) * 17 + 2 * bh];

        float4 hh[8];
#pragma unroll
        for (int kk = 0; kk < 4; kk++) {
            hh[2 * kk]     = hq[kk * 4];
            hh[2 * kk + 1] = hq[kk * 4 + 1];
        }
#pragma unroll
        for (int u = 0; u < 8; u++) {
            float4 w = wt[u * 16 + c];
#pragma unroll
            for (int kk = 0; kk < 4; kk++) {
                float wv = (kk == 0) ? w.x : (kk == 1) ? w.y : (kk == 2) ? w.z : w.w;
                float2 w2 = make_float2(wv, wv);
                float4 h0 = hh[2 * kk], h1 = hh[2 * kk + 1];
                dfma2(acc[u][0], w2, make_float2(h0.x, h0.y));
                dfma2(acc[u][1], w2, make_float2(h0.z, h0.w));
                dfma2(acc[u][2], w2, make_float2(h1.x, h1.y));
                dfma2(acc[u][3], w2, make_float2(h1.z, h1.w));
            }
        }
    }

    // reduce-scatter: rows over masks 4,2,1; pairs over 8
    float2 r4[4][4];
    {
        bool hi = (lane & 4) != 0;
#pragma unroll
        for (int u = 0; u < 4; u++)
#pragma unroll
            for (int p = 0; p < 4; p++) {
                float2 give = hi ? acc[u][p] : acc[u + 4][p];
                float2 mine = hi ? acc[u + 4][p] : acc[u][p];
                float2 got;
                got.x = __shfl_xor_sync(0xffffffffu, give.x, 4);
                got.y = __shfl_xor_sync(0xffffffffu, give.y, 4);
                r4[u][p] = make_float2(mine.x + got.x, mine.y + got.y);
            }
    }
    float2 r2[2][4];
    {
        bool hi = (lane & 2) != 0;
#pragma unroll
        for (int u = 0; u < 2; u++)
#pragma unroll
            for (int p = 0; p < 4; p++) {
                float2 give = hi ? r4[u][p] : r4[u + 2][p];
                float2 mine = hi ? r4[u + 2][p] : r4[u][p];
                float2 got;
                got.x = __shfl_xor_sync(0xffffffffu, give.x, 2);
                got.y = __shfl_xor_sync(0xffffffffu, give.y, 2);
                r2[u][p] = make_float2(mine.x + got.x, mine.y + got.y);
            }
    }
    float2 r1[4];
    {
        bool hi = (lane & 1) != 0;
#pragma unroll
        for (int p = 0; p < 4; p++) {
            float2 give = hi ? r2[0][p] : r2[1][p];
            float2 mine = hi ? r2[1][p] : r2[0][p];
            float2 got;
            got.x = __shfl_xor_sync(0xffffffffu, give.x, 1);
            got.y = __shfl_xor_sync(0xffffffffu, give.y, 1);
            r1[p] = make_float2(mine.x + got.x, mine.y + got.y);
        }
    }
    float2 rf[2];
    {
        bool hi = (lane & 8) != 0;
#pragma unroll
        for (int p = 0; p < 2; p++) {
            float2 give = hi ? r1[p] : r1[p + 2];
            float2 mine = hi ? r1[p + 2] : r1[p];
            float2 got;
            got.x = __shfl_xor_sync(0xffffffffu, give.x, 8);
            got.y = __shfl_xor_sync(0xffffffffu, give.y, 8);
            rf[p] = make_float2(mine.x + got.x, mine.y + got.y);
        }
    }

    int r = row0 + (lane & 7);
    if (r < NROWS) {
        float bias = b2[r];
        int i = r & 1, rem = r >> 1;
        int cc = rem / L0, l = rem - cc * L0;
        float4 o;
        o.x = tanhf(rf[0].x + bias);
        o.y = tanhf(rf[0].y + bias);
        o.z = tanhf(rf[1].x + bias);
        o.w = tanhf(rf[1].y + bias);
        *(float4*)&g_a[(size_t)((i * CF + cc) * L0 + l) * BATCH + 4 * (lane >> 3)] = o;
    }
}

// ---------------- Stage 3: ConvT #0 (16->16) + tanh — j=4, single-buffer, occ-boosted ----------------
// DRAM=1.6% (L2-resident): no prefetch double-buffer needed; spend regs on
// occupancy instead (target 5-6 blocks/SM = 20-24 warps vs 16).
__global__ __launch_bounds__(128, 5) void k_conv0(
    const float* __restrict__ ctw0, const float* __restrict__ ctb0)
{
    int i   = blockIdx.y;
    int tid = threadIdx.x;
    __shared__ float ws[CF * CF * 33];
    for (int t = tid; t < CF * CF * KS; t += 128) {
        int ci = t >> 9, co = (t >> 5) & 15, k = t & 31;
        ws[(ci * 16 + co) * 33 + k] = ctw0[i * (CF * CF * KS) + t];
    }
    __syncthreads();

    int bp = tid & 7;
    int co = tid >> 3;
    int q0 = blockIdx.x * 4;

    float2 acc[4][4];
#pragma unroll
    for (int j = 0; j < 4; j++)
#pragma unroll
        for (int ph = 0; ph < 4; ph++) acc[j][ph] = make_float2(0.f, 0.f);

#pragma unroll 1
    for (int ci = 0; ci < CF; ci++) {
        const float* src = g_a + (size_t)((i * CF + ci) * L0) * BATCH + 2 * bp;
        float2 inv[11];
#pragma unroll
        for (int t = 0; t < 11; t++) {
            int l = q0 - 3 + t;
            inv[t] = (l >= 0 && l <= L0 - 1) ? *(const float2*)(src + (size_t)l * BATCH)
                                             : make_float2(0.f, 0.f);
        }
        const float* wsp = &ws[(ci * 16 + co) * 33];
#pragma unroll
        for (int s = 0; s < 8; s++)
#pragma unroll
            for (int ph = 0; ph < 4; ph++) {
                float wv = wsp[ph + 4 * s];
                float2 w2 = make_float2(wv, wv);
#pragma unroll
                for (int j = 0; j < 4; j++) dfma2(acc[j][ph], w2, inv[j + 7 - s]);
            }
    }

    float bias = ctb0[i * CF + co];
#pragma unroll
    for (int j = 0; j < 4; j++)
#pragma unroll
        for (int ph = 0; ph < 4; ph++) {
            int o = 4 * (q0 + j) + ph;
            if (o < L1OUT) {
                float2 v;
                v.x = tanhf(acc[j][ph].x + bias);
                v.y = tanhf(acc[j][ph].y + bias);
                *(float2*)&g_c0[(size_t)((i * CF + co) * L1OUT + o) * BATCH + 2 * bp] = v;
            }
        }
}

// ---------------- Stage 4: ConvT #1 (16->1) + tanh — validated j=4 direct (21.9us) ----------------
__global__ __launch_bounds__(256) void k_conv1(
    const float* __restrict__ ctw1, const float* __restrict__ ctb1)
{
    int i   = blockIdx.y;
    int tid = threadIdx.x;
    __shared__ float wv[CF * KS];
    for (int t = tid; t < CF * KS; t += 256) wv[t] = ctw1[i * (CF * KS) + t];
    __syncthreads();

    int bp = tid & 7;
    int qi = tid >> 3;
    int q  = blockIdx.x * 128 + qi * 4;

    float2 acc[4][4];
#pragma unroll
    for (int j = 0; j < 4; j++)
#pragma unroll
        for (int ph = 0; ph < 4; ph++) acc[j][ph] = make_float2(0.f, 0.f);

#pragma unroll 1
    for (int ci = 0; ci < CF; ci++) {
        const float* src = g_c0 + (size_t)((i * CF + ci) * L1OUT) * BATCH + 2 * bp;
        float2 inv[11];
#pragma unroll
        for (int t = 0; t < 11; t++) {
            int l = q - 3 + t;
            inv[t] = (l >= 0 && l <= L1OUT - 1) ? *(const float2*)(src + (size_t)l * BATCH)
                                                : make_float2(0.f, 0.f);
        }
        const float* wp = &wv[ci * 32];
#pragma unroll
        for (int s = 0; s < 8; s++)
#pragma unroll
            for (int ph = 0; ph < 4; ph++) {
                float2 w2 = make_float2(wp[ph + 4 * s], wp[ph + 4 * s]);
#pragma unroll
                for (int j = 0; j < 4; j++) dfma2(acc[j][ph], w2, inv[j + 7 - s]);
            }
    }

    float bias = ctb1[i];
#pragma unroll
    for (int j = 0; j < 4; j++)
#pragma unroll
        for (int ph = 0; ph < 4; ph++) {
            int o = 4 * (q + j) + ph;
            float2 v;
            v.x = tanhf(acc[j][ph].x + bias);
            v.y = tanhf(acc[j][ph].y + bias);
            *(float2*)&g_c1[(size_t)(i * N_NODES + o) * BATCH + 2 * bp] = v;
        }
}

// ---------------- Stage 5: gather + combine ----------------
__global__ __launch_bounds__(256) void k_gather(
    const float* __restrict__ sps_w, const float* __restrict__ sps_b,
    const float* __restrict__ final_w, const float* __restrict__ final_b,
    const float* __restrict__ out_w, const float* __restrict__ out_b,
    const int* __restrict__ ord, float* __restrict__ out)
{
    __shared__ float gs[SFC][258][17];
    int tid = threadIdx.x;
    int n0  = blockIdx.x * 256;

    for (int t = tid; t < SFC * 258; t += 256) {
        int i  = (t >= 258);
        int tt = t - i * 258;
        int n  = n0 - 1 + tt;
        n = n < 0 ? 0 : (n > N_NODES - 1 ? N_NODES - 1 : n);
        int idx = ord[i * N_NODES + n];
        const float4* s4 = (const float4*)&g_c1[(size_t)(i * N_NODES + idx) * BATCH];
        float tmp[16];
        *(float4*)&tmp[0]  = s4[0];
        *(float4*)&tmp[4]  = s4[1];
        *(float4*)&tmp[8]  = s4[2];
        *(float4*)&tmp[12] = s4[3];
        float* row = gs[i][tt];
#pragma unroll
        for (int b = 0; b < 16; b++) row[b] = tmp[b];
    }
    __syncthreads();

    int n = n0 + tid;
    float w[SFC][3], sb[SFC];
#pragma unroll
    for (int i = 0; i < SFC; i++) {
        const float* wp = &sps_w[(size_t)(i * N_NODES + n) * 3];
        w[i][0] = wp[0]; w[i][1] = wp[1]; w[i][2] = wp[2];
        sb[i] = sps_b[i * N_NODES + n];
    }
    float fw0 = final_w[2 * n], fw1 = final_w[2 * n + 1];
    float fb = final_b[n], ow = out_w[n], ob = out_b[n];

#pragma unroll
    for (int b = 0; b < BATCH; b++) {
        float z0 = tanhf(gs[0][tid][b] * w[0][0] + gs[0][tid + 1][b] * w[0][1]
                       + gs[0][tid + 2][b] * w[0][2] + sb[0]);
        float z1 = tanhf(gs[1][tid][b] * w[1][0] + gs[1][tid + 1][b] * w[1][1]
                       + gs[1][tid + 2][b] * w[1][2] + sb[1]);
        float zz = tanhf(z0 * fw0 + z1 * fw1 + fb);
        out[(size_t)b * N_NODES + n] = zz * ow + ob;
    }
}

// ---------------- launch ----------------
extern "C" void kernel_launch(void* const* d_in, const int* in_sizes, int n_in,
                              void* d_out, int out_size)
{
    const float* x       = (const float*)d_in[0];
    const float* W1      = (const float*)d_in[1];
    const float* b1      = (const float*)d_in[2];
    const float* W2      = (const float*)d_in[3];
    const float* b2      = (const float*)d_in[4];
    const float* ctw0    = (const float*)d_in[5];
    const float* ctb0    = (const float*)d_in[6];
    const float* ctw1    = (const float*)d_in[7];
    const float* ctb1    = (const float*)d_in[8];
    const float* sps_w   = (const float*)d_in[9];
    const float* sps_b   = (const float*)d_in[10];
    const float* final_w = (const float*)d_in[11];
    const float* final_b = (const float*)d_in[12];
    const float* out_w   = (const float*)d_in[13];
    const float* out_b   = (const float*)d_in[14];
    const int*   ord     = (const int*)d_in[15];
    float* out = (float*)d_out;

    static int smem_set = 0;
    if (!smem_set) {
        cudaFuncSetAttribute(k_gemm2, cudaFuncAttributeMaxDynamicSharedMemorySize,
                             G2_SMEM);
        smem_set = 1;
    }

    k_gemm1<<<32, 256>>>(x, W1, b1);
    k_nop<<<1, 32>>>();   // single spacer: profiled slot (4th launch) = k_conv0
    k_gemm2<<<(NROWS + 63) / 64, 256, G2_SMEM>>>(W2, b2);
    k_conv0<<<dim3(1025, SFC), 128>>>(ctw0, ctb0);
    k_conv1<<<dim3(128, SFC), 256>>>(ctw1, ctb1);
    k_gather<<<dim3(256, 1), 256>>>(sps_w, sps_b, final_w, final_b,
                                    out_w, out_b, ord, out);
}